// round 16
// baseline (speedup 1.0000x reference)
#include <cuda_runtime.h>
#include <cuda_bf16.h>
#include <cstdint>

#define Cc 128
#define Hh 128
#define Ww 256
#define Bb 8
#define Kk 9
#define CSTRIDE (Hh * Ww)          // 32768
#define BSTRIDE (Cc * Hh * Ww)     // 4194304

// Per-(batch, px, step) completion counters (4 co-block CTAs each). Reset per pass.
__device__ unsigned g_cnt[Bb][4][256];
// Transposed-state scratch: [b][c][w][h]
__device__ float g_tmp[(size_t)Bb * BSTRIDE];

__device__ __forceinline__ unsigned ld_cg_u32(const unsigned* p) {
    unsigned v;
    asm volatile("ld.global.cg.u32 %0, [%1];" : "=r"(v) : "l"(p));
    return v;
}
// mma.sync m16n8k16 row.col f32.bf16.bf16.f32 (fallback HMMA on sm_103)
__device__ __forceinline__ void mma16816(float* d, const uint32_t* a, const uint32_t* b) {
    asm volatile(
        "mma.sync.aligned.m16n8k16.row.col.f32.bf16.bf16.f32 "
        "{%0,%1,%2,%3}, {%4,%5,%6,%7}, {%8,%9}, {%0,%1,%2,%3};"
        : "+f"(d[0]), "+f"(d[1]), "+f"(d[2]), "+f"(d[3])
        : "r"(a[0]), "r"(a[1]), "r"(a[2]), "r"(a[3]), "r"(b[0]), "r"(b[1]));
}
// Split (a,b) into packed bf16 hi/lo words; low half = a (even ci), high = b (odd ci).
__device__ __forceinline__ void bfsplit2(float a, float b, uint32_t& hw, uint32_t& lw) {
    __nv_bfloat16 ha = __float2bfloat16(a), hb = __float2bfloat16(b);
    float ra = a - __bfloat162float(ha), rb = b - __bfloat162float(hb);
    __nv_bfloat16 la = __float2bfloat16(ra), lb = __float2bfloat16(rb);
    hw = (uint32_t)__bfloat16_as_ushort(ha) | ((uint32_t)__bfloat16_as_ushort(hb) << 16);
    lw = (uint32_t)__bfloat16_as_ushort(la) | ((uint32_t)__bfloat16_as_ushort(lb) << 16);
}

// Persistent directional pass, warp-level bf16 MMA, 3-term hi/lo split.
// Same math/K-mapping as R13/R14 (proven). New data layouts for issue economy:
//  - A fragment-major: per (tile, mt, lane) 4 hi + 4 lo words contiguous ->
//    2x LDS.128 per k-tile (was 8x LDS.32).
//  - Window hi dup-paired: wq[ci2][j] = u64(wp[j], wp[j+4]) -> B-hi fragment
//    is one LDS.64; entry lo-halves double as the flat array (tap-8 tiles).
//    lo stays flat (2x LDS.32).
// 512 thr = 16 warps = 2 mt x 4 nb x 2 ks (K halves); 3 accumulator sets.
template <int PT, int NF>
__global__ __launch_bounds__(512, 1)
void pass_mma(float* __restrict__ state, const float* __restrict__ wt,
              int q0, int dq, int nq, int L, int SQ)
{
    constexpr int WWIN = PT + 20;          // u32 window words per ci2 (84 / 52)
    constexpr int A2N  = 64 * 2 * 32 * 8;  // 32768 u32, fragment-major
    constexpr int A8N  = 8 * 2 * 32 * 8;   // 4096 u32
    constexpr int WQN  = 2 * 64 * WWIN;    // u32 (u64 entries)
    constexpr int WLN  = 64 * WWIN;
    constexpr int NCH  = WWIN / 4;         // staging float4 chunks per ci2
    constexpr int AC   = NF * 4;           // accum floats per thread

    extern __shared__ uint32_t smu[];
    uint32_t* A2f = smu;                   // [t][mt][lane][hi4|lo4]
    uint32_t* A8f = A2f + A2N;
    uint32_t* wq  = A8f + A8N;             // hi dup-pairs (u64 entries)
    uint32_t* wpL = wq + WQN;              // lo flat
    float*    s_red = reinterpret_cast<float*>(wpL + WLN);

    const int tid = threadIdx.x, wid = tid >> 5, lid = tid & 31;
    const int g = lid >> 2, c = lid & 3;
    const int mt = wid & 1, nb = (wid >> 1) & 3, ks = wid >> 3;

    const int px = blockIdx.x, cby = blockIdx.y, b = blockIdx.z;
    const int p0 = px * PT, co0 = cby * 32;
    const int npx = gridDim.x;
    float* base = state + (size_t)b * BSTRIDE;

    // ---- pre-pack weights, fragment-major, once per pass ----
    for (int idx = tid; idx < 16384; idx += 512) {          // A2: taps 0..7
        int q = idx & 3, lane = (idx >> 2) & 31, mtt = (idx >> 7) & 1, t = idx >> 8;
        int gg = lane >> 2, cc = lane & 3;
        int m  = mtt * 16 + gg + ((q & 1) ? 8 : 0);
        int kk = cc + ((q & 2) ? 4 : 0);
        const float* w0 = wt + (size_t)(co0 + m) * (Cc * Kk);
        uint32_t hw, lw;
        bfsplit2(w0[(2 * t) * Kk + kk], w0[(2 * t + 1) * Kk + kk], hw, lw);
        int bs = ((t * 2 + mtt) * 32 + lane) * 8;
        A2f[bs + q] = hw;
        A2f[bs + 4 + q] = lw;
    }
    for (int idx = tid; idx < 2048; idx += 512) {           // A8: tap 8
        int q = idx & 3, lane = (idx >> 2) & 31, mtt = (idx >> 7) & 1, t8 = idx >> 8;
        int gg = lane >> 2, cc = lane & 3;
        int m   = mtt * 16 + gg + ((q & 1) ? 8 : 0);
        int ci2 = 8 * t8 + cc + ((q & 2) ? 4 : 0);
        const float* w0 = wt + (size_t)(co0 + m) * (Cc * Kk) + 8;
        uint32_t hw, lw;
        bfsplit2(w0[(2 * ci2) * Kk], w0[(2 * ci2 + 1) * Kk], hw, lw);
        int bs = ((t8 * 2 + mtt) * 32 + lane) * 8;
        A8f[bs + q] = hw;
        A8f[bs + 4 + q] = lw;
    }
    __syncthreads();

    for (int s = 1; s < nq; s++) {
        // ---- wait for rows s-1 of p-blocks {px-1, px, px+1} (4 CTAs each) ----
        if (s > 1 && tid < 3) {
            int pxn = px + tid - 1;
            if (pxn >= 0 && pxn < npx) {
                const unsigned* f = &g_cnt[b][pxn][s - 1];
                while (ld_cg_u32(f) < 4u) __nanosleep(20);
            }
        }
        __syncthreads();
        __threadfence();   // acquire

        const float* prev = base + (size_t)(q0 + (s - 1) * dq) * SQ;
        float*       cur  = base + (size_t)(q0 + s * dq) * SQ;

        // ---- stage window: lo flat, hi dup-paired ----
        for (int u = tid; u < 64 * NCH; u += 512) {
            int ci2 = u / NCH, j0 = (u - ci2 * NCH) * 4;
            int p = p0 - 4 + j0;
            const float* ra = prev + (size_t)(2 * ci2) * CSTRIDE;
            const float* rb = ra + CSTRIDE;
            float av[4], bv[4];
            if (p >= 0 && p + 4 <= L) {
                float4 va = __ldcg(reinterpret_cast<const float4*>(ra + p));
                float4 vb = __ldcg(reinterpret_cast<const float4*>(rb + p));
                av[0]=va.x; av[1]=va.y; av[2]=va.z; av[3]=va.w;
                bv[0]=vb.x; bv[1]=vb.y; bv[2]=vb.z; bv[3]=vb.w;
            } else {
#pragma unroll
                for (int j = 0; j < 4; j++) {
                    bool in = (unsigned)(p + j) < (unsigned)L;
                    av[j] = in ? __ldcg(ra + p + j) : 0.f;
                    bv[j] = in ? __ldcg(rb + p + j) : 0.f;
                }
            }
            uint32_t hw[4], lw[4];
#pragma unroll
            for (int j = 0; j < 4; j++) bfsplit2(av[j], bv[j], hw[j], lw[j]);
            *reinterpret_cast<uint4*>(wpL + ci2 * WWIN + j0) =
                make_uint4(lw[0], lw[1], lw[2], lw[3]);
            const int eb = ci2 * WWIN + j0;
#pragma unroll
            for (int j = 0; j < 4; j++) wq[2 * (eb + j)] = hw[j];      // lo halves
            if (j0 >= 4) {
#pragma unroll
                for (int j = 0; j < 4; j++) wq[2 * (eb + j - 4) + 1] = hw[j];
            }
        }

        // ---- prefetch cur_old (ks=0 warps only; exclusive region) ----
        float2 oldv[NF][2];
        if (ks == 0) {
#pragma unroll
            for (int nf = 0; nf < NF; nf++) {
                int pf = nb * (8 * NF) + nf * 8;
                const float* r0 = cur + (size_t)(co0 + mt * 16 + g) * CSTRIDE
                                      + p0 + pf + 2 * c;
                oldv[nf][0] = __ldcg(reinterpret_cast<const float2*>(r0));
                oldv[nf][1] = __ldcg(reinterpret_cast<const float2*>(r0 + 8 * CSTRIDE));
            }
        }
        __syncthreads();

        // ---- compute: half-K per warp, 3 independent accumulator sets ----
        float dhh[NF][4], dhl[NF][4], dlh[NF][4];
#pragma unroll
        for (int nf = 0; nf < NF; nf++)
#pragma unroll
            for (int j = 0; j < 4; j++) {
                dhh[nf][j] = 0.f; dhl[nf][j] = 0.f; dlh[nf][j] = 0.f;
            }

#pragma unroll 2
        for (int tt = 0; tt < 32; tt++) {
            const int t = ks * 32 + tt;
            const uint32_t* ap = A2f + (size_t)((t * 2 + mt) * 32 + lid) * 8;
            uint4 AH = *reinterpret_cast<const uint4*>(ap);
            uint4 AL = *reinterpret_cast<const uint4*>(ap + 4);
            uint32_t ah[4] = {AH.x, AH.y, AH.z, AH.w};
            uint32_t al[4] = {AL.x, AL.y, AL.z, AL.w};
#pragma unroll
            for (int nf = 0; nf < NF; nf++) {
                int e = t * WWIN + nb * (8 * NF) + nf * 8 + g + c;
                uint2 BH = *reinterpret_cast<const uint2*>(wq + 2 * e);
                uint32_t bh[2] = {BH.x, BH.y};
                uint32_t bl[2] = {wpL[e], wpL[e + 4]};
                mma16816(dhh[nf], ah, bh);
                mma16816(dhl[nf], ah, bl);
                mma16816(dlh[nf], al, bh);
            }
        }
#pragma unroll
        for (int t8i = 0; t8i < 4; t8i++) {
            const int t8 = ks * 4 + t8i;
            const uint32_t* ap = A8f + (size_t)((t8 * 2 + mt) * 32 + lid) * 8;
            uint4 AH = *reinterpret_cast<const uint4*>(ap);
            uint4 AL = *reinterpret_cast<const uint4*>(ap + 4);
            uint32_t ah[4] = {AH.x, AH.y, AH.z, AH.w};
            uint32_t al[4] = {AL.x, AL.y, AL.z, AL.w};
#pragma unroll
            for (int nf = 0; nf < NF; nf++) {
                int j  = nb * (8 * NF) + nf * 8 + g + 8;
                int e1 = (8 * t8 + c) * WWIN + j;
                int e2 = e1 + 4 * WWIN;
                uint32_t bh[2] = {wq[2 * e1], wq[2 * e2]};   // entry lo-halves
                uint32_t bl[2] = {wpL[e1], wpL[e2]};
                mma16816(dhh[nf], ah, bh);
                mma16816(dhl[nf], ah, bl);
                mma16816(dlh[nf], al, bh);
            }
        }

        // ---- fold terms; ks=1 deposit partials ----
        float d[NF][4];
#pragma unroll
        for (int nf = 0; nf < NF; nf++)
#pragma unroll
            for (int j = 0; j < 4; j++)
                d[nf][j] = dhh[nf][j] + dhl[nf][j] + dlh[nf][j];

        if (ks == 1) {
            float* r = s_red + ((mt * 4 + nb) * 32 + lid) * AC;
#pragma unroll
            for (int nf = 0; nf < NF; nf++)
                *reinterpret_cast<float4*>(r + nf * 4) =
                    make_float4(d[nf][0], d[nf][1], d[nf][2], d[nf][3]);
        }
        __syncthreads();

        if (ks == 0) {
            const float* r = s_red + ((mt * 4 + nb) * 32 + lid) * AC;
#pragma unroll
            for (int nf = 0; nf < NF; nf++) {
                float4 rv = *reinterpret_cast<const float4*>(r + nf * 4);
                d[nf][0] += rv.x; d[nf][1] += rv.y;
                d[nf][2] += rv.z; d[nf][3] += rv.w;
            }
            // ---- epilogue: cur = cur_old + relu(conv) ----
#pragma unroll
            for (int nf = 0; nf < NF; nf++) {
                int pf = nb * (8 * NF) + nf * 8;
                float* r0 = cur + (size_t)(co0 + mt * 16 + g) * CSTRIDE
                                + p0 + pf + 2 * c;
                float2 e0, e1;
                e0.x = oldv[nf][0].x + fmaxf(d[nf][0], 0.f);
                e0.y = oldv[nf][0].y + fmaxf(d[nf][1], 0.f);
                e1.x = oldv[nf][1].x + fmaxf(d[nf][2], 0.f);
                e1.y = oldv[nf][1].y + fmaxf(d[nf][3], 0.f);
                *reinterpret_cast<float2*>(r0)               = e0;
                *reinterpret_cast<float2*>(r0 + 8 * CSTRIDE) = e1;
            }
        }

        // ---- publish ----
        __syncthreads();
        if (tid == 0) {
            __threadfence();
            atomicAdd(&g_cnt[b][px][s], 1u);
        }
    }
}

// [b,c,R,C] -> [b,c,C,R], tiled 32x32.
__global__ __launch_bounds__(256)
void transpose_kernel(const float* __restrict__ src, float* __restrict__ dst,
                      int R, int C)
{
    __shared__ float t[32][33];
    const long plane = blockIdx.z;
    const float* s = src + plane * (long)R * C;
    float*       d = dst + plane * (long)R * C;
    const int c0 = blockIdx.x * 32, r0 = blockIdx.y * 32;
    const int x = threadIdx.x & 31, y = threadIdx.x >> 5;
#pragma unroll
    for (int i = 0; i < 32; i += 8)
        t[y + i][x] = s[(long)(r0 + y + i) * C + c0 + x];
    __syncthreads();
#pragma unroll
    for (int i = 0; i < 32; i += 8)
        d[(long)(c0 + y + i) * R + r0 + x] = t[x][y + i];
}

extern "C" void kernel_launch(void* const* d_in, const int* in_sizes, int n_in,
                              void* d_out, int out_size)
{
    const float* x       = (const float*)d_in[0];
    const float* w_down  = (const float*)d_in[1];
    const float* w_up    = (const float*)d_in[2];
    const float* w_right = (const float*)d_in[3];
    const float* w_left  = (const float*)d_in[4];
    float* out = (float*)d_out;

    // u32 counts: A2f 32768 + A8f 4096 + wq 2*64*WWIN + wpL 64*WWIN (+ s_red)
    const int SMEM_W = (32768 + 4096 + 3 * 64 * 84) * 4 + 8 * 32 * 8 * 4;  // 220160
    const int SMEM_H = (32768 + 4096 + 3 * 64 * 52) * 4 + 8 * 32 * 4 * 4;  // 191488
    cudaFuncSetAttribute((const void*)pass_mma<64, 2>,
                         cudaFuncAttributeMaxDynamicSharedMemorySize, SMEM_W);
    cudaFuncSetAttribute((const void*)pass_mma<32, 1>,
                         cudaFuncAttributeMaxDynamicSharedMemorySize, SMEM_H);

    void *cntp, *tmpp;
    cudaGetSymbolAddress(&cntp, g_cnt);
    cudaGetSymbolAddress(&tmpp, g_tmp);
    float* tmp = (float*)tmpp;

    cudaMemcpyAsync(out, x, (size_t)Bb * BSTRIDE * sizeof(float),
                    cudaMemcpyDeviceToDevice);

    dim3 blk(512), grid(4, 4, Bb);

    // Pass 1: down. [b,c,h,w]: conv along w (L=256), rec over h (SQ=256).
    cudaMemsetAsync(cntp, 0, sizeof(g_cnt));
    pass_mma<64, 2><<<grid, blk, SMEM_W>>>(out, w_down, 0, +1, Hh, Ww, Ww);

    // Pass 2: up.
    cudaMemsetAsync(cntp, 0, sizeof(g_cnt));
    pass_mma<64, 2><<<grid, blk, SMEM_W>>>(out, w_up, Hh - 1, -1, Hh, Ww, Ww);

    // Transpose to [b,c,w,h]
    transpose_kernel<<<dim3(Ww / 32, Hh / 32, Bb * Cc), dim3(256)>>>(out, tmp, Hh, Ww);

    // Pass 3: right. conv along h (L=128), rec over w (SQ=128).
    cudaMemsetAsync(cntp, 0, sizeof(g_cnt));
    pass_mma<32, 1><<<grid, blk, SMEM_H>>>(tmp, w_right, 0, +1, Ww, Hh, Hh);

    // Pass 4: left.
    cudaMemsetAsync(cntp, 0, sizeof(g_cnt));
    pass_mma<32, 1><<<grid, blk, SMEM_H>>>(tmp, w_left, Ww - 1, -1, Ww, Hh, Hh);

    // Transpose back to [b,c,h,w]
    transpose_kernel<<<dim3(Hh / 32, Ww / 32, Bb * Cc), dim3(256)>>>(tmp, out, Ww, Hh);
}

// round 17
// speedup vs baseline: 1.4901x; 1.4901x over previous
#include <cuda_runtime.h>
#include <cuda_bf16.h>
#include <cstdint>

#define Cc 128
#define Hh 128
#define Ww 256
#define Bb 8
#define Kk 9
#define CSTRIDE (Hh * Ww)          // 32768
#define BSTRIDE (Cc * Hh * Ww)     // 4194304

// Per-(batch, px, step) completion counters (4 co-block CTAs each). Reset per pass.
__device__ unsigned g_cnt[Bb][4][256];
// Transposed-state scratch: [b][c][w][h]
__device__ float g_tmp[(size_t)Bb * BSTRIDE];

__device__ __forceinline__ unsigned ld_cg_u32(const unsigned* p) {
    unsigned v;
    asm volatile("ld.global.cg.u32 %0, [%1];" : "=r"(v) : "l"(p));
    return v;
}
// mma.sync m16n8k16 row.col f32.bf16.bf16.f32 (fallback HMMA on sm_103)
__device__ __forceinline__ void mma16816(float* d, const uint32_t* a, const uint32_t* b) {
    asm volatile(
        "mma.sync.aligned.m16n8k16.row.col.f32.bf16.bf16.f32 "
        "{%0,%1,%2,%3}, {%4,%5,%6,%7}, {%8,%9}, {%0,%1,%2,%3};"
        : "+f"(d[0]), "+f"(d[1]), "+f"(d[2]), "+f"(d[3])
        : "r"(a[0]), "r"(a[1]), "r"(a[2]), "r"(a[3]), "r"(b[0]), "r"(b[1]));
}
// Split (a,b) into packed bf16 hi/lo words; low half = a (even ci), high = b (odd ci).
__device__ __forceinline__ void bfsplit2(float a, float b, uint32_t& hw, uint32_t& lw) {
    __nv_bfloat16 ha = __float2bfloat16(a), hb = __float2bfloat16(b);
    float ra = a - __bfloat162float(ha), rb = b - __bfloat162float(hb);
    __nv_bfloat16 la = __float2bfloat16(ra), lb = __float2bfloat16(rb);
    hw = (uint32_t)__bfloat16_as_ushort(ha) | ((uint32_t)__bfloat16_as_ushort(hb) << 16);
    lw = (uint32_t)__bfloat16_as_ushort(la) | ((uint32_t)__bfloat16_as_ushort(lb) << 16);
}

// Persistent directional pass, warp-level bf16 MMA, 3-term hi/lo split.
// R14 math/layouts verbatim; warp decomposition rebalanced for LDS economy:
// 512 thr = 16 warps = 2 mt x 2 nb x 4 ks. NF = PT/16 n-frags per warp.
// Each warp covers quarter-K (16 A2-tiles + 2 A8-tiles); A fragments are
// loaded once per tile and reused for NF B-fragments (A crossbar cost /4 vs
// R14). ks>0 warps deposit folded partials; ks=0 warps reduce + epilogue.
template <int PT, int NF>
__global__ __launch_bounds__(512, 1)
void pass_mma(float* __restrict__ state, const float* __restrict__ wt,
              int q0, int dq, int nq, int L, int SQ)
{
    constexpr int WWIN = PT + 20;          // u32 window words per ci2 (84 / 52)
    constexpr int RS2  = 516;              // A2 row stride (u32)
    constexpr int RS8  = 68;               // A8 row stride
    constexpr int A2N  = 32 * RS2;         // 16512
    constexpr int A8N  = 32 * RS8;         // 2176
    constexpr int WPN  = 64 * WWIN;
    constexpr int NCH  = WWIN / 4;         // staging float4 chunks per ci2
    constexpr int AC   = NF * 4;           // accum floats per thread

    extern __shared__ uint32_t smu[];
    uint32_t* A2h = smu;
    uint32_t* A2l = A2h + A2N;
    uint32_t* A8h = A2l + A2N;
    uint32_t* A8l = A8h + A8N;
    uint32_t* wpH = A8l + A8N;
    uint32_t* wpL = wpH + WPN;
    float*    s_red = reinterpret_cast<float*>(wpL + WPN);  // [12 warp][32 lane][AC]

    const int tid = threadIdx.x, wid = tid >> 5, lid = tid & 31;
    const int g = lid >> 2, c = lid & 3;
    const int mt = wid & 1, nb = (wid >> 1) & 1, ks = wid >> 2;

    const int px = blockIdx.x, cby = blockIdx.y, b = blockIdx.z;
    const int p0 = px * PT, co0 = cby * 32;
    const int npx = gridDim.x;
    float* base = state + (size_t)b * BSTRIDE;

    // ---- stage weights (split + ci-pair packed) once per pass ----
    for (int idx = tid; idx < 32 * Cc * Kk; idx += 512) {
        int m = idx / (Cc * Kk), r = idx - m * (Cc * Kk);
        int ci = r / Kk, kk = r - ci * Kk;
        float f = wt[(size_t)(co0 + m) * (Cc * Kk) + r];
        __nv_bfloat16 h = __float2bfloat16(f);
        float rf = f - __bfloat162float(h);
        __nv_bfloat16 l = __float2bfloat16(rf);
        int ci2 = ci >> 1, par = ci & 1;
        if (kk < 8) {
            int u = m * RS2 + ci2 * 8 + kk;
            reinterpret_cast<__nv_bfloat16*>(A2h)[u * 2 + par] = h;
            reinterpret_cast<__nv_bfloat16*>(A2l)[u * 2 + par] = l;
        } else {
            int u = m * RS8 + ci2;
            reinterpret_cast<__nv_bfloat16*>(A8h)[u * 2 + par] = h;
            reinterpret_cast<__nv_bfloat16*>(A8l)[u * 2 + par] = l;
        }
    }
    __syncthreads();

    const int aB2 = (mt * 16 + g) * RS2 + c;
    const int aB8 = (mt * 16 + g) * RS8 + c;

    for (int s = 1; s < nq; s++) {
        // ---- wait for rows s-1 of p-blocks {px-1, px, px+1} (4 CTAs each) ----
        if (s > 1 && tid < 3) {
            int pxn = px + tid - 1;
            if (pxn >= 0 && pxn < npx) {
                const unsigned* f = &g_cnt[b][pxn][s - 1];
                while (ld_cg_u32(f) < 4u) __nanosleep(20);
            }
        }
        __syncthreads();
        __threadfence();   // acquire

        const float* prev = base + (size_t)(q0 + (s - 1) * dq) * SQ;
        float*       cur  = base + (size_t)(q0 + s * dq) * SQ;

        // ---- stage window: wp[ci2][j] = packed {x[2ci2][p], x[2ci2+1][p]} ----
        for (int u = tid; u < 64 * NCH; u += 512) {
            int ci2 = u / NCH, j0 = (u - ci2 * NCH) * 4;
            int p = p0 - 4 + j0;
            const float* ra = prev + (size_t)(2 * ci2) * CSTRIDE;
            const float* rb = ra + CSTRIDE;
            float av[4], bv[4];
            if (p >= 0 && p + 4 <= L) {
                float4 va = __ldcg(reinterpret_cast<const float4*>(ra + p));
                float4 vb = __ldcg(reinterpret_cast<const float4*>(rb + p));
                av[0]=va.x; av[1]=va.y; av[2]=va.z; av[3]=va.w;
                bv[0]=vb.x; bv[1]=vb.y; bv[2]=vb.z; bv[3]=vb.w;
            } else {
#pragma unroll
                for (int j = 0; j < 4; j++) {
                    bool in = (unsigned)(p + j) < (unsigned)L;
                    av[j] = in ? __ldcg(ra + p + j) : 0.f;
                    bv[j] = in ? __ldcg(rb + p + j) : 0.f;
                }
            }
            uint32_t hw[4], lw[4];
#pragma unroll
            for (int j = 0; j < 4; j++) bfsplit2(av[j], bv[j], hw[j], lw[j]);
            *reinterpret_cast<uint4*>(wpH + ci2 * WWIN + j0) =
                make_uint4(hw[0], hw[1], hw[2], hw[3]);
            *reinterpret_cast<uint4*>(wpL + ci2 * WWIN + j0) =
                make_uint4(lw[0], lw[1], lw[2], lw[3]);
        }

        // ---- prefetch cur_old (ks=0 warps only; exclusive region) ----
        float2 oldv[NF][2];
        if (ks == 0) {
#pragma unroll
            for (int nf = 0; nf < NF; nf++) {
                int pf = nb * (8 * NF) + nf * 8;
                const float* r0 = cur + (size_t)(co0 + mt * 16 + g) * CSTRIDE
                                      + p0 + pf + 2 * c;
                oldv[nf][0] = __ldcg(reinterpret_cast<const float2*>(r0));
                oldv[nf][1] = __ldcg(reinterpret_cast<const float2*>(r0 + 8 * CSTRIDE));
            }
        }
        __syncthreads();

        // ---- compute: quarter-K per warp, 3 independent accumulator sets ----
        float dhh[NF][4], dhl[NF][4], dlh[NF][4];
#pragma unroll
        for (int nf = 0; nf < NF; nf++)
#pragma unroll
            for (int j = 0; j < 4; j++) {
                dhh[nf][j] = 0.f; dhl[nf][j] = 0.f; dlh[nf][j] = 0.f;
            }

#pragma unroll 2
        for (int tt = 0; tt < 16; tt++) {
            const int t = ks * 16 + tt;
            uint32_t ah[4], al[4];
            int ia = aB2 + t * 8;
            ah[0] = A2h[ia];     ah[1] = A2h[ia + 8 * RS2];
            ah[2] = A2h[ia + 4]; ah[3] = A2h[ia + 4 + 8 * RS2];
            al[0] = A2l[ia];     al[1] = A2l[ia + 8 * RS2];
            al[2] = A2l[ia + 4]; al[3] = A2l[ia + 4 + 8 * RS2];
#pragma unroll
            for (int nf = 0; nf < NF; nf++) {
                int jb = t * WWIN + nb * (8 * NF) + nf * 8 + g + c;
                uint32_t bh[2] = { wpH[jb], wpH[jb + 4] };
                uint32_t bl[2] = { wpL[jb], wpL[jb + 4] };
                mma16816(dhh[nf], ah, bh);
                mma16816(dhl[nf], ah, bl);
                mma16816(dlh[nf], al, bh);
            }
        }
#pragma unroll
        for (int t8i = 0; t8i < 2; t8i++) {
            const int t8 = ks * 2 + t8i;
            uint32_t ah[4], al[4];
            int ia = aB8 + t8 * 8;
            ah[0] = A8h[ia];     ah[1] = A8h[ia + 8 * RS8];
            ah[2] = A8h[ia + 4]; ah[3] = A8h[ia + 4 + 8 * RS8];
            al[0] = A8l[ia];     al[1] = A8l[ia + 8 * RS8];
            al[2] = A8l[ia + 4]; al[3] = A8l[ia + 4 + 8 * RS8];
#pragma unroll
            for (int nf = 0; nf < NF; nf++) {
                int jb = (8 * t8 + c) * WWIN + nb * (8 * NF) + nf * 8 + g + 8;
                uint32_t bh[2] = { wpH[jb], wpH[jb + 4 * WWIN] };
                uint32_t bl[2] = { wpL[jb], wpL[jb + 4 * WWIN] };
                mma16816(dhh[nf], ah, bh);
                mma16816(dhl[nf], ah, bl);
                mma16816(dlh[nf], al, bh);
            }
        }

        // ---- fold terms; ks>0 deposit partials ----
        float d[NF][4];
#pragma unroll
        for (int nf = 0; nf < NF; nf++)
#pragma unroll
            for (int j = 0; j < 4; j++)
                d[nf][j] = dhh[nf][j] + dhl[nf][j] + dlh[nf][j];

        if (ks > 0) {
            float* r = s_red + (((ks - 1) * 4 + mt * 2 + nb) * 32 + lid) * AC;
#pragma unroll
            for (int nf = 0; nf < NF; nf++)
                *reinterpret_cast<float4*>(r + nf * 4) =
                    make_float4(d[nf][0], d[nf][1], d[nf][2], d[nf][3]);
        }
        __syncthreads();

        if (ks == 0) {
#pragma unroll
            for (int j2 = 0; j2 < 3; j2++) {
                const float* r = s_red + ((j2 * 4 + mt * 2 + nb) * 32 + lid) * AC;
#pragma unroll
                for (int nf = 0; nf < NF; nf++) {
                    float4 rv = *reinterpret_cast<const float4*>(r + nf * 4);
                    d[nf][0] += rv.x; d[nf][1] += rv.y;
                    d[nf][2] += rv.z; d[nf][3] += rv.w;
                }
            }
            // ---- epilogue: cur = cur_old + relu(conv) ----
#pragma unroll
            for (int nf = 0; nf < NF; nf++) {
                int pf = nb * (8 * NF) + nf * 8;
                float* r0 = cur + (size_t)(co0 + mt * 16 + g) * CSTRIDE
                                + p0 + pf + 2 * c;
                float2 e0, e1;
                e0.x = oldv[nf][0].x + fmaxf(d[nf][0], 0.f);
                e0.y = oldv[nf][0].y + fmaxf(d[nf][1], 0.f);
                e1.x = oldv[nf][1].x + fmaxf(d[nf][2], 0.f);
                e1.y = oldv[nf][1].y + fmaxf(d[nf][3], 0.f);
                *reinterpret_cast<float2*>(r0)               = e0;
                *reinterpret_cast<float2*>(r0 + 8 * CSTRIDE) = e1;
            }
        }

        // ---- publish ----
        __syncthreads();
        if (tid == 0) {
            __threadfence();
            atomicAdd(&g_cnt[b][px][s], 1u);
        }
    }
}

// [b,c,R,C] -> [b,c,C,R], tiled 32x32.
__global__ __launch_bounds__(256)
void transpose_kernel(const float* __restrict__ src, float* __restrict__ dst,
                      int R, int C)
{
    __shared__ float t[32][33];
    const long plane = blockIdx.z;
    const float* s = src + plane * (long)R * C;
    float*       d = dst + plane * (long)R * C;
    const int c0 = blockIdx.x * 32, r0 = blockIdx.y * 32;
    const int x = threadIdx.x & 31, y = threadIdx.x >> 5;
#pragma unroll
    for (int i = 0; i < 32; i += 8)
        t[y + i][x] = s[(long)(r0 + y + i) * C + c0 + x];
    __syncthreads();
#pragma unroll
    for (int i = 0; i < 32; i += 8)
        d[(long)(c0 + y + i) * R + r0 + x] = t[x][y + i];
}

extern "C" void kernel_launch(void* const* d_in, const int* in_sizes, int n_in,
                              void* d_out, int out_size)
{
    const float* x       = (const float*)d_in[0];
    const float* w_down  = (const float*)d_in[1];
    const float* w_up    = (const float*)d_in[2];
    const float* w_right = (const float*)d_in[3];
    const float* w_left  = (const float*)d_in[4];
    float* out = (float*)d_out;

    // u32 counts: A2(2*16512) + A8(2*2176) + wp(2*64*WWIN) + s_red(12*32*AC)
    const int SMEM_W = (2 * 16512 + 2 * 2176 + 2 * 64 * 84) * 4 + 12 * 32 * 16 * 4; // 217088
    const int SMEM_H = (2 * 16512 + 2 * 2176 + 2 * 64 * 52) * 4 + 12 * 32 * 8 * 4;  // 188416
    cudaFuncSetAttribute((const void*)pass_mma<64, 4>,
                         cudaFuncAttributeMaxDynamicSharedMemorySize, SMEM_W);
    cudaFuncSetAttribute((const void*)pass_mma<32, 2>,
                         cudaFuncAttributeMaxDynamicSharedMemorySize, SMEM_H);

    void *cntp, *tmpp;
    cudaGetSymbolAddress(&cntp, g_cnt);
    cudaGetSymbolAddress(&tmpp, g_tmp);
    float* tmp = (float*)tmpp;

    cudaMemcpyAsync(out, x, (size_t)Bb * BSTRIDE * sizeof(float),
                    cudaMemcpyDeviceToDevice);

    dim3 blk(512), grid(4, 4, Bb);

    // Pass 1: down. [b,c,h,w]: conv along w (L=256), rec over h (SQ=256).
    cudaMemsetAsync(cntp, 0, sizeof(g_cnt));
    pass_mma<64, 4><<<grid, blk, SMEM_W>>>(out, w_down, 0, +1, Hh, Ww, Ww);

    // Pass 2: up.
    cudaMemsetAsync(cntp, 0, sizeof(g_cnt));
    pass_mma<64, 4><<<grid, blk, SMEM_W>>>(out, w_up, Hh - 1, -1, Hh, Ww, Ww);

    // Transpose to [b,c,w,h]
    transpose_kernel<<<dim3(Ww / 32, Hh / 32, Bb * Cc), dim3(256)>>>(out, tmp, Hh, Ww);

    // Pass 3: right. conv along h (L=128), rec over w (SQ=128).
    cudaMemsetAsync(cntp, 0, sizeof(g_cnt));
    pass_mma<32, 2><<<grid, blk, SMEM_H>>>(tmp, w_right, 0, +1, Ww, Hh, Hh);

    // Pass 4: left.
    cudaMemsetAsync(cntp, 0, sizeof(g_cnt));
    pass_mma<32, 2><<<grid, blk, SMEM_H>>>(tmp, w_left, Ww - 1, -1, Ww, Hh, Hh);

    // Transpose back to [b,c,h,w]
    transpose_kernel<<<dim3(Hh / 32, Ww / 32, Bb * Cc), dim3(256)>>>(tmp, out, Ww, Hh);
}